// round 6
// baseline (speedup 1.0000x reference)
#include <cuda_runtime.h>
#include <cuda_bf16.h>

#define NB 32
#define WPB 8
#define THREADS (WPB * 32)
#define STRIDE 36   // padded row; floats [32..35] of row j hold h[j] (overlay)

__device__ __forceinline__ float clamp01(float x) {
    return fminf(fmaxf(x, 0.0f), 1.0f);
}

__device__ __forceinline__ float sqrt_approx(float x) {
    float r;
    asm("sqrt.approx.f32 %0, %1;" : "=f"(r) : "f"(x));   // sqrt.approx(+0)=+0
    return r;
}

__device__ __forceinline__ void cp_async16(void* smem_dst, const void* gmem_src) {
    unsigned sa = (unsigned)__cvta_generic_to_shared(smem_dst);
    asm volatile("cp.async.cg.shared.global [%0], [%1], 16;\n"
                 :: "r"(sa), "l"(gmem_src) : "memory");
}

__global__ __launch_bounds__(THREADS, 6)
void BioTokenMucusSim_kernel(const float* __restrict__ h,
                             const float* __restrict__ W,
                             const float* __restrict__ stim,
                             float* __restrict__ h_out,
                             float* __restrict__ W_out,
                             int n_pairs)
{
    // 8 warps x 32 rows x 36 floats = 36864 B/block -> 6 blocks/SM
    __shared__ float wsh[WPB][NB * STRIDE];

    const int warp = threadIdx.x >> 5;
    const int lane = threadIdx.x & 31;
    const int pair = blockIdx.x * WPB + warp;
    if (pair >= n_pairs) return;

    const float* Wp = W + (size_t)pair * (NB * NB);
    float* ws = wsh[warp];

    const int qr = lane >> 3;        // row-in-group
    const int qc = (lane & 7) * 4;   // float4 col offset

    // ---- W tile + h: direct global->shared via cp.async (no reg staging) ----
    #pragma unroll
    for (int t = 0; t < 8; ++t) {
        const int r = t * 4 + qr;
        cp_async16(ws + r * STRIDE + qc, Wp + r * NB + qc);
    }
    cp_async16(ws + lane * STRIDE + 32, h + (size_t)pair * NB * 4 + lane * 4);
    asm volatile("cp.async.commit_group;\n" ::: "memory");

    const float s = stim[(size_t)pair * NB + lane];   // overlap with copies

    asm volatile("cp.async.wait_group 0;\n" ::: "memory");
    __syncwarp();

    // diag := 0 (update pass forces it 0 anyway); read own h back
    ws[lane * STRIDE + lane] = 0.0f;
    const float4 hv = *(const float4*)(ws + lane * STRIDE + 32);
    __syncwarp();

    // ---- masked matvec: row from shared, h via 1-wf broadcasts ----
    float ifx = 0.f, ify = 0.f, ifz = 0.f, ifw = 0.f, wsum = 0.f;
    #pragma unroll
    for (int t = 0; t < 8; ++t) {
        const float4 w4 = *(const float4*)(ws + lane * STRIDE + t * 4);
        const float wq[4] = {w4.x, w4.y, w4.z, w4.w};
        #pragma unroll
        for (int e = 0; e < 4; ++e) {
            const int j = t * 4 + e;
            const float4 hj = *(const float4*)(ws + j * STRIDE + 32);
            ifx  += wq[e] * hj.x;
            ify  += wq[e] * hj.y;
            ifz  += wq[e] * hj.z;
            ifw  += wq[e] * hj.w;
            wsum += wq[e];
        }
    }
    const float inv = 1.0f / (wsum + 1e-8f);
    const float En = ifx * inv, Pn = ify * inv, Gn = ifz * inv, Ln = ifw * inv;

    // ---- channel update ----
    const float E = hv.x, P = hv.y, G = hv.z, L = hv.w;
    const float E_new = clamp01(E + 0.3f * s - 0.4f * P - 0.2f * G);
    const float P_new = clamp01(P + 0.5f * s + 0.3f * (Pn - P) - 0.2f * E);
    const float G_new = clamp01(G + 0.4f * E * (1.0f - P) + 0.2f * (Gn - G) - 0.3f * P);
    const float good  = 0.5f * En + 0.5f * Gn;
    const float L_new = clamp01(L + 0.4f * good + 0.3f * (Ln - L) - 0.3f * P);

    const float4 hn = make_float4(E_new, P_new, G_new, L_new);
    ((float4*)(h_out + (size_t)pair * NB * 4))[lane] = hn;

    __syncwarp();                                  // matvec h reads done
    *(float4*)(ws + lane * STRIDE + 32) = hn;      // publish h_new
    __syncwarp();

    // ---- fused W-update + coalesced store ----
    // wn = clamp01(0.95*W + 0.05*(L_i + L_j) * dist(i,j)), diag = 0
    float hjx[4], hjy[4], hjz[4], hjw[4], lj05[4];
    #pragma unroll
    for (int e = 0; e < 4; ++e) {
        const float4 v = *(const float4*)(ws + (qc + e) * STRIDE + 32);
        hjx[e] = v.x; hjy[e] = v.y; hjz[e] = v.z; hjw[e] = v.w;
        lj05[e] = 0.05f * v.w;
    }

    float* Wo = W_out + (size_t)pair * (NB * NB);
    #pragma unroll
    for (int t = 0; t < 8; ++t) {
        const int r = t * 4 + qr;
        const float4 w  = *(const float4*)(ws + r * STRIDE + qc);
        const float4 hr = *(const float4*)(ws + r * STRIDE + 32);
        const float hr05 = 0.05f * hr.w;
        const float wq[4] = {w.x, w.y, w.z, w.w};
        float out[4];
        #pragma unroll
        for (int e = 0; e < 4; ++e) {
            const float dx = hr.x - hjx[e];
            const float dy = hr.y - hjy[e];
            const float dz = hr.z - hjz[e];
            const float dw = hr.w - hjw[e];
            float sq = dx * dx;
            sq = fmaf(dy, dy, sq);
            sq = fmaf(dz, dz, sq);
            sq = fmaf(dw, dw, sq);
            const float dist = sqrt_approx(sq);
            const float a = hr05 + lj05[e];
            float wn = fmaf(a, dist, 0.95f * wq[e]);
            wn = clamp01(wn);
            if (r == qc + e) wn = 0.0f;            // diagonal
            out[e] = wn;
        }
        *(float4*)(Wo + r * NB + qc) = make_float4(out[0], out[1], out[2], out[3]);
    }
}

extern "C" void kernel_launch(void* const* d_in, const int* in_sizes, int n_in,
                              void* d_out, int out_size) {
    const float* h    = (const float*)d_in[0];  // [B,S,32,4]
    const float* W    = (const float*)d_in[1];  // [B,S,32,32]
    const float* stim = (const float*)d_in[2];  // [B,S,32]

    const int n_pairs = in_sizes[2] / NB;       // B*S

    float* h_out = (float*)d_out;                       // h_new first
    float* W_out = (float*)d_out + (size_t)in_sizes[0]; // then W_new

    const int blocks = (n_pairs + WPB - 1) / WPB;
    BioTokenMucusSim_kernel<<<blocks, THREADS>>>(h, W, stim, h_out, W_out, n_pairs);
}